// round 12
// baseline (speedup 1.0000x reference)
#include <cuda_runtime.h>
#include <cuda_fp16.h>
#include <cstdint>

// Problem constants
#define NIMG   8
#define CDIM   256
#define HWDIM  9216
#define TT     32
#define VV     256
#define TV     8192
#define TILE   128
#define NTILES 64

// chunked smem: 2-stage ring of 128x64 A+B chunks, XOR-swizzled
#define CHUNK_BYTES 16384                      // 128 rows * 64 halves * 2B
#define SMEM_BYTES_RING (4 * CHUNK_BYTES)      // A0,B0,A1,B1 = 64 KB

#define MAXNEG 2016
#define MAXPOS 2080

#define LOG2E    1.4426950408889634f
#define LOG2E_X2 2.8853900817779268f           // exp(2a-2) = 2^(a*L2 - L2)

// Persistent device scratch
__device__ __half g_feats[(size_t)TV * CDIM];
__device__ float g_neg_sum[TV];
__device__ float g_row_loss[TV];
__device__ int   g_is64;
__device__ int   g_negcnt;
__device__ int   g_poscnt;
__device__ unsigned short g_negpairs[MAXNEG];
__device__ unsigned short g_pospairs[MAXPOS];

__device__ __forceinline__ float fexp2(float x) {
    float r;
    asm("ex2.approx.f32 %0, %1;" : "=f"(r) : "f"(x));
    return r;
}

#define CP_ASYNC16(dst, src) \
    asm volatile("cp.async.cg.shared.global [%0], [%1], 16;" :: "r"(dst), "l"(src))
#define CP_COMMIT()  asm volatile("cp.async.commit_group;" ::: "memory")
#define CP_WAIT(n)   asm volatile("cp.async.wait_group %0;" :: "n"(n) : "memory")

// ---------------------------------------------------------------------------
// K_prep: 1 block. dtype detect + zero accumulators + PARALLEL worklist build.
// ---------------------------------------------------------------------------
__global__ void k_prep(const unsigned int* __restrict__ w,
                       const int* __restrict__ labels) {
    int tid = threadIdx.x;
    unsigned acc = 0;
    for (int i = tid; i < 4096; i += 256) acc |= w[2 * i + 1];
    #pragma unroll
    for (int o = 16; o; o >>= 1) acc |= __shfl_xor_sync(0xFFFFFFFFu, acc, o);
    __shared__ unsigned sh[8];
    if ((tid & 31) == 0) sh[tid >> 5] = acc;
    for (int i = tid; i < TV; i += 256) { g_neg_sum[i] = 0.0f; g_row_loss[i] = 0.0f; }
    if (tid == 0) { g_negcnt = 0; g_poscnt = 0; }
    __syncthreads();
    if (tid == 0) {
        unsigned t = 0;
        #pragma unroll
        for (int i = 0; i < 8; i++) t |= sh[i];
        g_is64 = (t == 0) ? 1 : 0;
    }
    __shared__ int slab[TT];
    if (tid < TT) slab[tid] = labels[tid];
    __syncthreads();
    for (int idx = tid; idx < NTILES * NTILES; idx += 256) {
        int rt = idx >> 6, ct = idx & 63;
        if (ct < rt) continue;
        unsigned short pr = (unsigned short)((rt << 8) | ct);
        if (slab[rt >> 1] == slab[ct >> 1]) g_pospairs[atomicAdd(&g_poscnt, 1)] = pr;
        else                                g_negpairs[atomicAdd(&g_negcnt, 1)] = pr;
    }
}

// ---------------------------------------------------------------------------
// K1: gather + L2-normalize -> fp16. Warp per sample; 8 strided loads.
// ---------------------------------------------------------------------------
__global__ void __launch_bounds__(256)
k_gather(const float* __restrict__ features,
         const int* __restrict__ batch_inds,
         const void* __restrict__ sample_inds) {
    __shared__ __half stage[8 * 264];
    int tid  = threadIdx.x;
    int lane = tid & 31;
    int wrp  = tid >> 5;
    int i = blockIdx.x * 8 + wrp;
    int t = i >> 8;
    int v = i & 255;
    int b = batch_inds[t] & (NIMG - 1);

    long long s;
    if (g_is64) s = ((const long long*)sample_inds)[t * VV + v];
    else        s = (long long)((const int*)sample_inds)[t * VV + v];
    if (s < 0) s = 0;
    if (s >= HWDIM) s = HWDIM - 1;

    const float* base = features + (size_t)b * CDIM * HWDIM + (size_t)s;
    float f[8];
    #pragma unroll
    for (int k = 0; k < 8; k++)
        f[k] = base[(size_t)(lane + 32 * k) * HWDIM];

    float ss = 0.0f;
    #pragma unroll
    for (int k = 0; k < 8; k++) ss += f[k] * f[k];
    #pragma unroll
    for (int o = 16; o; o >>= 1) ss += __shfl_xor_sync(0xFFFFFFFFu, ss, o);

    float inv = 1.0f / fmaxf(sqrtf(ss), 1e-12f);
    #pragma unroll
    for (int k = 0; k < 8; k++)
        stage[wrp * 264 + lane + 32 * k] = __float2half(f[k] * inv);
    __syncwarp();
    uint4 val = *(uint4*)&stage[wrp * 264 + lane * 8];
    *(uint4*)(g_feats + (size_t)i * CDIM + lane * 8) = val;
}

// ---------------------------------------------------------------------------
// swizzled ldmatrix / mma helpers
// ---------------------------------------------------------------------------
__device__ __forceinline__ void ldmA_sw(uint32_t a[4], uint32_t base,
                                        int rowBase, int k0, int lane) {
    int row = rowBase + (lane & 15);
    int u   = (k0 >> 3) + (lane >> 4);
    uint32_t addr = base + (uint32_t)((row * 8 + (u ^ (row & 7))) * 16);
    asm volatile("ldmatrix.sync.aligned.m8n8.x4.shared.b16 {%0,%1,%2,%3}, [%4];"
                 : "=r"(a[0]), "=r"(a[1]), "=r"(a[2]), "=r"(a[3]) : "r"(addr));
}
__device__ __forceinline__ void ldmB_sw(uint32_t b[2], uint32_t base,
                                        int nBase, int k0, int lane) {
    int l   = lane & 15;
    int row = nBase + (l & 7);
    int u   = (k0 >> 3) + (l >> 3);
    uint32_t addr = base + (uint32_t)((row * 8 + (u ^ (row & 7))) * 16);
    asm volatile("ldmatrix.sync.aligned.m8n8.x2.shared.b16 {%0,%1}, [%2];"
                 : "=r"(b[0]), "=r"(b[1]) : "r"(addr));
}
__device__ __forceinline__ void mma_f16acc(uint32_t c[2], const uint32_t a[4],
                                           const uint32_t b[2]) {
    asm volatile("mma.sync.aligned.m16n8k16.row.col.f16.f16.f16.f16 "
                 "{%0,%1},{%2,%3,%4,%5},{%6,%7},{%0,%1};"
                 : "+r"(c[0]), "+r"(c[1])
                 : "r"(a[0]), "r"(a[1]), "r"(a[2]), "r"(a[3]), "r"(b[0]), "r"(b[1]));
}
__device__ __forceinline__ void mma_f32acc(float c[4], const uint32_t a[4],
                                           const uint32_t b[2]) {
    asm volatile("mma.sync.aligned.m16n8k16.row.col.f32.f16.f16.f32 "
                 "{%0,%1,%2,%3},{%4,%5,%6,%7},{%8,%9},{%0,%1,%2,%3};"
                 : "+f"(c[0]), "+f"(c[1]), "+f"(c[2]), "+f"(c[3])
                 : "r"(a[0]), "r"(a[1]), "r"(a[2]), "r"(a[3]), "r"(b[0]), "r"(b[1]));
}

// cp.async one K-chunk stage (A rows rtRow.., B rows ctRow.., K chunk kc)
__device__ __forceinline__ void stage_load(uint32_t sA, uint32_t sB,
                                           int rtRow, int ctRow, int kc, int tid) {
    #pragma unroll
    for (int x = 0; x < 4; x++) {
        int idx = tid + x * 256;
        int row = idx >> 3;
        int u   = idx & 7;
        uint32_t doff = (uint32_t)((row * 8 + (u ^ (row & 7))) * 16);
        const char* srcA = (const char*)(g_feats
                          + ((size_t)(rtRow + row) << 8) + kc * 64 + u * 8);
        const char* srcB = (const char*)(g_feats
                          + ((size_t)(ctRow + row) << 8) + kc * 64 + u * 8);
        CP_ASYNC16(sA + doff, srcA);
        CP_ASYNC16(sB + doff, srcB);
    }
}

// ---------------------------------------------------------------------------
// K2 (k_negpair): streaming version. Grid-stride over the neg worklist;
// each block pushes its pairs through ONE continuous 2-stage cp.async ring
// (chunk c+2 issued before pair epilogue -> epilogue hides under loads).
// ---------------------------------------------------------------------------
extern "C" __global__ void __launch_bounds__(256, 2)
k_negpair() {
    int npairs = g_negcnt;
    int bx = blockIdx.x, G = gridDim.x;
    if (bx >= npairs) return;
    int mycnt = (npairs - 1 - bx) / G + 1;
    int nch = mycnt * 4;

    extern __shared__ __align__(16) char dynsm[];
    uint32_t smb = (uint32_t)__cvta_generic_to_shared(dynsm);
    uint32_t sAb[2] = { smb, smb + 2 * CHUNK_BYTES };
    uint32_t sBb[2] = { smb + CHUNK_BYTES, smb + 3 * CHUNK_BYTES };

    int tid  = threadIdx.x;
    int lane = tid & 31;
    int wid  = tid >> 5;
    int wr   = wid >> 2;
    int wc   = wid & 3;

    uint32_t acc[4][4][2];

    // issue chunk c of this block's stream
    #define ISSUE(c) do { \
        unsigned _p = g_negpairs[bx + ((c) >> 2) * G]; \
        int _rtR = (int)(_p >> 8) * TILE, _ctR = (int)(_p & 255) * TILE; \
        int _buf = (c) & 1; \
        stage_load(sAb[_buf], sBb[_buf], _rtR, _ctR, (c) & 3, tid); \
        CP_COMMIT(); \
    } while (0)

    ISSUE(0);
    if (nch > 1) ISSUE(1);

    for (int c = 0; c < nch; c++) {
        if ((c & 3) == 0) {
            #pragma unroll
            for (int mt = 0; mt < 4; mt++)
                #pragma unroll
                for (int nt = 0; nt < 4; nt++) { acc[mt][nt][0] = 0u; acc[mt][nt][1] = 0u; }
        }
        if (c + 1 < nch) CP_WAIT(1); else CP_WAIT(0);
        __syncthreads();
        int buf = c & 1;
        #pragma unroll
        for (int ks = 0; ks < 4; ks++) {
            int k0 = ks * 16;
            uint32_t a[4][4], b[4][2];
            #pragma unroll
            for (int mt = 0; mt < 4; mt++)
                ldmA_sw(a[mt], sAb[buf], wr * 64 + mt * 16, k0, lane);
            #pragma unroll
            for (int nt = 0; nt < 4; nt++)
                ldmB_sw(b[nt], sBb[buf], wc * 32 + nt * 8, k0, lane);
            #pragma unroll
            for (int mt = 0; mt < 4; mt++)
                #pragma unroll
                for (int nt = 0; nt < 4; nt++)
                    mma_f16acc(acc[mt][nt], a[mt], b[nt]);
        }
        __syncthreads();
        if (c + 2 < nch) ISSUE(c + 2);

        if ((c & 3) == 3) {
            // epilogue for pair (c>>2) — overlaps with in-flight loads
            unsigned p = g_negpairs[bx + (c >> 2) * G];
            int rtRow = (int)(p >> 8) * TILE, ctRow = (int)(p & 255) * TILE;

            float rAcc[4][2] = {};
            float cAcc[4][2] = {};
            #pragma unroll
            for (int mt = 0; mt < 4; mt++)
                #pragma unroll
                for (int nt = 0; nt < 4; nt++)
                    #pragma unroll
                    for (int h = 0; h < 2; h++) {
                        __half2 pk = *(__half2*)&acc[mt][nt][h];
                        float a0 = __low2float(pk), a1 = __high2float(pk);
                        float v0 = fexp2(fmaf(a0, LOG2E_X2, -LOG2E_X2));
                        float v1 = fexp2(fmaf(a1, LOG2E_X2, -LOG2E_X2));
                        rAcc[mt][h] += v0 + v1;
                        cAcc[nt][0] += v0;
                        cAcc[nt][1] += v1;
                    }
            #pragma unroll
            for (int mt = 0; mt < 4; mt++)
                #pragma unroll
                for (int h = 0; h < 2; h++) {
                    float v = rAcc[mt][h];
                    v += __shfl_xor_sync(0xFFFFFFFFu, v, 1);
                    v += __shfl_xor_sync(0xFFFFFFFFu, v, 2);
                    if ((lane & 3) == 0) {
                        int row = rtRow + wr * 64 + mt * 16 + (lane >> 2) + h * 8;
                        atomicAdd(&g_neg_sum[row], v);
                    }
                }
            #pragma unroll
            for (int nt = 0; nt < 4; nt++)
                #pragma unroll
                for (int cc = 0; cc < 2; cc++) {
                    float v = cAcc[nt][cc];
                    v += __shfl_xor_sync(0xFFFFFFFFu, v, 4);
                    v += __shfl_xor_sync(0xFFFFFFFFu, v, 8);
                    v += __shfl_xor_sync(0xFFFFFFFFu, v, 16);
                    if (lane < 4) {
                        int col = ctRow + wc * 32 + nt * 8 + 2 * lane + cc;
                        atomicAdd(&g_neg_sum[col], v);
                    }
                }
        }
    }
    #undef ISSUE
}

// ---------------------------------------------------------------------------
// K3 (k_pos): chunked cp.async pipeline, f32 acc; grid-stride over worklist;
// symmetric scatter; logS / invS inline.
// ---------------------------------------------------------------------------
extern "C" __global__ void __launch_bounds__(256, 1)
k_pos() {
    int npairs = g_poscnt;

    extern __shared__ __align__(16) char dynsm[];
    uint32_t smb = (uint32_t)__cvta_generic_to_shared(dynsm);
    uint32_t sAb[2] = { smb, smb + 2 * CHUNK_BYTES };
    uint32_t sBb[2] = { smb + CHUNK_BYTES, smb + 3 * CHUNK_BYTES };

    int tid  = threadIdx.x;
    int lane = tid & 31;
    int wid  = tid >> 5;
    int wr   = wid >> 2;
    int wc   = wid & 3;

    for (int pi = blockIdx.x; pi < npairs; pi += gridDim.x) {
        unsigned p = g_pospairs[pi];
        int rt = (int)(p >> 8), ct = (int)(p & 255);
        bool diag = (rt == ct);
        int rtRow = rt * TILE, ctRow = ct * TILE;

        float acc[4][4][4];
        #pragma unroll
        for (int mt = 0; mt < 4; mt++)
            #pragma unroll
            for (int nt = 0; nt < 4; nt++)
                #pragma unroll
                for (int q = 0; q < 4; q++) acc[mt][nt][q] = 0.0f;

        stage_load(sAb[0], sBb[0], rtRow, ctRow, 0, tid); CP_COMMIT();
        stage_load(sAb[1], sBb[1], rtRow, ctRow, 1, tid); CP_COMMIT();

        #pragma unroll
        for (int kc = 0; kc < 4; kc++) {
            if (kc == 3) CP_WAIT(0); else CP_WAIT(1);
            __syncthreads();
            int buf = kc & 1;
            #pragma unroll
            for (int ks = 0; ks < 4; ks++) {
                int k0 = ks * 16;
                uint32_t a[4][4], b[4][2];
                #pragma unroll
                for (int mt = 0; mt < 4; mt++)
                    ldmA_sw(a[mt], sAb[buf], wr * 64 + mt * 16, k0, lane);
                #pragma unroll
                for (int nt = 0; nt < 4; nt++)
                    ldmB_sw(b[nt], sBb[buf], wc * 32 + nt * 8, k0, lane);
                #pragma unroll
                for (int mt = 0; mt < 4; mt++)
                    #pragma unroll
                    for (int nt = 0; nt < 4; nt++)
                        mma_f32acc(acc[mt][nt], a[mt], b[nt]);
            }
            __syncthreads();
            if (kc < 2) {
                stage_load(sAb[buf], sBb[buf], rtRow, ctRow, kc + 2, tid);
                CP_COMMIT();
            }
        }

        float cLog[4][2], cInv[4][2];
        float cSum[4][2] = {};
        #pragma unroll
        for (int nt = 0; nt < 4; nt++)
            #pragma unroll
            for (int cc = 0; cc < 2; cc++) {
                int col = ctRow + wc * 32 + nt * 8 + ((lane & 3) << 1) + cc;
                float S = g_neg_sum[col];
                cLog[nt][cc] = __logf(S);
                cInv[nt][cc] = 1.0f / S;
            }

        #pragma unroll
        for (int mt = 0; mt < 4; mt++) {
            #pragma unroll
            for (int h = 0; h < 2; h++) {
                int row  = rtRow + wr * 64 + mt * 16 + (lane >> 2) + h * 8;
                float Sr = g_neg_sum[row];
                float ls = __logf(Sr);
                float is = 1.0f / Sr;
                float rSum = 0.0f;
                #pragma unroll
                for (int nt = 0; nt < 4; nt++) {
                    #pragma unroll
                    for (int cc = 0; cc < 2; cc++) {
                        int col = ctRow + wc * 32 + nt * 8 + ((lane & 3) << 1) + cc;
                        if (diag && col == row) continue;
                        float a = acc[mt][nt][h * 2 + cc];
                        float l = fmaf(2.0f, a, -2.0f);
                        float e = fexp2(l * LOG2E);
                        float xr = e * is;
                        rSum += l - ls - xr + 0.5f * xr * xr;
                        if (!diag) {
                            float xc = e * cInv[nt][cc];
                            cSum[nt][cc] += l - cLog[nt][cc] - xc + 0.5f * xc * xc;
                        }
                    }
                }
                float v = rSum;
                v += __shfl_xor_sync(0xFFFFFFFFu, v, 1);
                v += __shfl_xor_sync(0xFFFFFFFFu, v, 2);
                if ((lane & 3) == 0) atomicAdd(&g_row_loss[row], v);
            }
        }
        if (!diag) {
            #pragma unroll
            for (int nt = 0; nt < 4; nt++)
                #pragma unroll
                for (int cc = 0; cc < 2; cc++) {
                    float v = cSum[nt][cc];
                    v += __shfl_xor_sync(0xFFFFFFFFu, v, 4);
                    v += __shfl_xor_sync(0xFFFFFFFFu, v, 8);
                    v += __shfl_xor_sync(0xFFFFFFFFu, v, 16);
                    if (lane < 4) {
                        int col = ctRow + wc * 32 + nt * 8 + 2 * lane + cc;
                        atomicAdd(&g_row_loss[col], v);
                    }
                }
        }
        __syncthreads();   // protect ring buffers before next pair's loads
    }
}

// ---------------------------------------------------------------------------
// K4: final reduction
// ---------------------------------------------------------------------------
__global__ void k_final(const int* __restrict__ labels, float* __restrict__ out) {
    __shared__ int   lab[TT];
    __shared__ float invpc[TT];
    __shared__ float ws[8];
    int tid = threadIdx.x;
    if (tid < TT) lab[tid] = labels[tid];
    __syncthreads();
    if (tid < TT) {
        int ns = 0;
        #pragma unroll
        for (int j = 0; j < TT; j++) ns += (lab[j] == lab[tid]);
        invpc[tid] = 1.0f / (float)(ns * VV - 1);
    }
    __syncthreads();

    float s = 0.0f;
    for (int i = tid; i < TV; i += 256) s += g_row_loss[i] * invpc[i >> 8];
    #pragma unroll
    for (int o = 16; o; o >>= 1) s += __shfl_xor_sync(0xFFFFFFFFu, s, o);
    if ((tid & 31) == 0) ws[tid >> 5] = s;
    __syncthreads();
    if (tid == 0) {
        float t = 0.0f;
        #pragma unroll
        for (int w = 0; w < 8; w++) t += ws[w];
        out[0] = -(t / (float)TV);
    }
}

// ---------------------------------------------------------------------------
extern "C" void kernel_launch(void* const* d_in, const int* in_sizes, int n_in,
                              void* d_out, int out_size) {
    const float* features    = (const float*)d_in[0];
    const int*   batch_inds  = (const int*)d_in[1];
    const void*  sample_inds = (const void*)d_in[2];
    const int*   labels      = (const int*)d_in[3];
    float*       out         = (float*)d_out;

    static bool attr_set = false;
    if (!attr_set) {
        cudaFuncSetAttribute(k_negpair, cudaFuncAttributeMaxDynamicSharedMemorySize, SMEM_BYTES_RING);
        cudaFuncSetAttribute(k_pos,     cudaFuncAttributeMaxDynamicSharedMemorySize, SMEM_BYTES_RING);
        attr_set = true;
    }

    k_prep<<<1, 256>>>((const unsigned int*)sample_inds, labels);
    k_gather<<<TV / 8, 256>>>(features, batch_inds, sample_inds);
    k_negpair<<<304, 256, SMEM_BYTES_RING>>>();
    k_pos<<<592, 256, SMEM_BYTES_RING>>>();
    k_final<<<1, 256>>>(labels, out);
}

// round 13
// speedup vs baseline: 1.6374x; 1.6374x over previous
#include <cuda_runtime.h>
#include <cuda_fp16.h>
#include <cstdint>

// Problem constants
#define NIMG   8
#define CDIM   256
#define HWDIM  9216
#define TT     32
#define VV     256
#define TV     8192
#define TILE   128
#define NTILES 64

// chunked smem: 2-stage ring of 128x64 A+B chunks, XOR-swizzled
#define CHUNK_BYTES 16384                      // 128 rows * 64 halves * 2B
#define SMEM_BYTES_RING (4 * CHUNK_BYTES)      // A0,B0,A1,B1 = 64 KB

#define MAXNEG 2016
#define MAXPOS 2080

#define LOG2E    1.4426950408889634f
#define LOG2E_X2 2.8853900817779268f           // exp(2a-2) = 2^(a*L2 - L2)

// Persistent device scratch
__device__ __half g_feats[(size_t)TV * CDIM];
__device__ float g_neg_sum[TV];
__device__ float g_row_loss[TV];
__device__ int   g_is64;
__device__ int   g_negcnt;
__device__ int   g_poscnt;
__device__ unsigned short g_negpairs[MAXNEG];
__device__ unsigned short g_pospairs[MAXPOS];

__device__ __forceinline__ float fexp2(float x) {
    float r;
    asm("ex2.approx.f32 %0, %1;" : "=f"(r) : "f"(x));
    return r;
}

#define CP_ASYNC16(dst, src) \
    asm volatile("cp.async.cg.shared.global [%0], [%1], 16;" :: "r"(dst), "l"(src))
#define CP_COMMIT()  asm volatile("cp.async.commit_group;" ::: "memory")
#define CP_WAIT(n)   asm volatile("cp.async.wait_group %0;" :: "n"(n) : "memory")

// ---------------------------------------------------------------------------
// K_prep: 1 block. dtype detect + zero accumulators + PARALLEL worklist build.
// ---------------------------------------------------------------------------
__global__ void k_prep(const unsigned int* __restrict__ w,
                       const int* __restrict__ labels) {
    int tid = threadIdx.x;
    unsigned acc = 0;
    for (int i = tid; i < 4096; i += 256) acc |= w[2 * i + 1];
    #pragma unroll
    for (int o = 16; o; o >>= 1) acc |= __shfl_xor_sync(0xFFFFFFFFu, acc, o);
    __shared__ unsigned sh[8];
    if ((tid & 31) == 0) sh[tid >> 5] = acc;
    for (int i = tid; i < TV; i += 256) { g_neg_sum[i] = 0.0f; g_row_loss[i] = 0.0f; }
    if (tid == 0) { g_negcnt = 0; g_poscnt = 0; }
    __syncthreads();
    if (tid == 0) {
        unsigned t = 0;
        #pragma unroll
        for (int i = 0; i < 8; i++) t |= sh[i];
        g_is64 = (t == 0) ? 1 : 0;
    }
    __shared__ int slab[TT];
    if (tid < TT) slab[tid] = labels[tid];
    __syncthreads();
    for (int idx = tid; idx < NTILES * NTILES; idx += 256) {
        int rt = idx >> 6, ct = idx & 63;
        if (ct < rt) continue;
        unsigned short pr = (unsigned short)((rt << 8) | ct);
        if (slab[rt >> 1] == slab[ct >> 1]) g_pospairs[atomicAdd(&g_poscnt, 1)] = pr;
        else                                g_negpairs[atomicAdd(&g_negcnt, 1)] = pr;
    }
}

// ---------------------------------------------------------------------------
// K1: gather + L2-normalize -> fp16. Warp per sample; 8 strided loads.
// ---------------------------------------------------------------------------
__global__ void __launch_bounds__(256)
k_gather(const float* __restrict__ features,
         const int* __restrict__ batch_inds,
         const void* __restrict__ sample_inds) {
    __shared__ __half stage[8 * 264];
    int tid  = threadIdx.x;
    int lane = tid & 31;
    int wrp  = tid >> 5;
    int i = blockIdx.x * 8 + wrp;
    int t = i >> 8;
    int v = i & 255;
    int b = batch_inds[t] & (NIMG - 1);

    long long s;
    if (g_is64) s = ((const long long*)sample_inds)[t * VV + v];
    else        s = (long long)((const int*)sample_inds)[t * VV + v];
    if (s < 0) s = 0;
    if (s >= HWDIM) s = HWDIM - 1;

    const float* base = features + (size_t)b * CDIM * HWDIM + (size_t)s;
    float f[8];
    #pragma unroll
    for (int k = 0; k < 8; k++)
        f[k] = base[(size_t)(lane + 32 * k) * HWDIM];

    float ss = 0.0f;
    #pragma unroll
    for (int k = 0; k < 8; k++) ss += f[k] * f[k];
    #pragma unroll
    for (int o = 16; o; o >>= 1) ss += __shfl_xor_sync(0xFFFFFFFFu, ss, o);

    float inv = 1.0f / fmaxf(sqrtf(ss), 1e-12f);
    #pragma unroll
    for (int k = 0; k < 8; k++)
        stage[wrp * 264 + lane + 32 * k] = __float2half(f[k] * inv);
    __syncwarp();
    uint4 val = *(uint4*)&stage[wrp * 264 + lane * 8];
    *(uint4*)(g_feats + (size_t)i * CDIM + lane * 8) = val;
}

// ---------------------------------------------------------------------------
// swizzled ldmatrix / mma helpers
// ---------------------------------------------------------------------------
__device__ __forceinline__ void ldmA_sw(uint32_t a[4], uint32_t base,
                                        int rowBase, int k0, int lane) {
    int row = rowBase + (lane & 15);
    int u   = (k0 >> 3) + (lane >> 4);
    uint32_t addr = base + (uint32_t)((row * 8 + (u ^ (row & 7))) * 16);
    asm volatile("ldmatrix.sync.aligned.m8n8.x4.shared.b16 {%0,%1,%2,%3}, [%4];"
                 : "=r"(a[0]), "=r"(a[1]), "=r"(a[2]), "=r"(a[3]) : "r"(addr));
}
__device__ __forceinline__ void ldmB_sw(uint32_t b[2], uint32_t base,
                                        int nBase, int k0, int lane) {
    int l   = lane & 15;
    int row = nBase + (l & 7);
    int u   = (k0 >> 3) + (l >> 3);
    uint32_t addr = base + (uint32_t)((row * 8 + (u ^ (row & 7))) * 16);
    asm volatile("ldmatrix.sync.aligned.m8n8.x2.shared.b16 {%0,%1}, [%2];"
                 : "=r"(b[0]), "=r"(b[1]) : "r"(addr));
}
__device__ __forceinline__ void mma_f16acc(uint32_t c[2], const uint32_t a[4],
                                           const uint32_t b[2]) {
    asm volatile("mma.sync.aligned.m16n8k16.row.col.f16.f16.f16.f16 "
                 "{%0,%1},{%2,%3,%4,%5},{%6,%7},{%0,%1};"
                 : "+r"(c[0]), "+r"(c[1])
                 : "r"(a[0]), "r"(a[1]), "r"(a[2]), "r"(a[3]), "r"(b[0]), "r"(b[1]));
}
__device__ __forceinline__ void mma_f32acc(float c[4], const uint32_t a[4],
                                           const uint32_t b[2]) {
    asm volatile("mma.sync.aligned.m16n8k16.row.col.f32.f16.f16.f32 "
                 "{%0,%1,%2,%3},{%4,%5,%6,%7},{%8,%9},{%0,%1,%2,%3};"
                 : "+f"(c[0]), "+f"(c[1]), "+f"(c[2]), "+f"(c[3])
                 : "r"(a[0]), "r"(a[1]), "r"(a[2]), "r"(a[3]), "r"(b[0]), "r"(b[1]));
}

// cp.async one K-chunk stage (A rows rtRow.., B rows ctRow.., K chunk kc)
__device__ __forceinline__ void stage_load(uint32_t sA, uint32_t sB,
                                           int rtRow, int ctRow, int kc, int tid) {
    #pragma unroll
    for (int x = 0; x < 4; x++) {
        int idx = tid + x * 256;
        int row = idx >> 3;
        int u   = idx & 7;
        uint32_t doff = (uint32_t)((row * 8 + (u ^ (row & 7))) * 16);
        const char* srcA = (const char*)(g_feats
                          + ((size_t)(rtRow + row) << 8) + kc * 64 + u * 8);
        const char* srcB = (const char*)(g_feats
                          + ((size_t)(ctRow + row) << 8) + kc * 64 + u * 8);
        CP_ASYNC16(sA + doff, srcA);
        CP_ASYNC16(sB + doff, srcB);
    }
}

// ---------------------------------------------------------------------------
// K2 (k_negpair): R11 version. One different-label pair per block;
// fully-unrolled 4-chunk 2-stage cp.async ring; f16 accumulators.
// ---------------------------------------------------------------------------
extern "C" __global__ void __launch_bounds__(256, 2)
k_negpair() {
    int bx = blockIdx.x;
    if (bx >= g_negcnt) return;
    unsigned p = g_negpairs[bx];
    int rt = (int)(p >> 8), ct = (int)(p & 255);

    extern __shared__ __align__(16) char dynsm[];
    uint32_t smb = (uint32_t)__cvta_generic_to_shared(dynsm);
    uint32_t sAb[2] = { smb, smb + 2 * CHUNK_BYTES };
    uint32_t sBb[2] = { smb + CHUNK_BYTES, smb + 3 * CHUNK_BYTES };

    int tid  = threadIdx.x;
    int lane = tid & 31;
    int wid  = tid >> 5;
    int wr   = wid >> 2;
    int wc   = wid & 3;
    int rtRow = rt * TILE, ctRow = ct * TILE;

    uint32_t acc[4][4][2];
    #pragma unroll
    for (int mt = 0; mt < 4; mt++)
        #pragma unroll
        for (int nt = 0; nt < 4; nt++) { acc[mt][nt][0] = 0u; acc[mt][nt][1] = 0u; }

    stage_load(sAb[0], sBb[0], rtRow, ctRow, 0, tid); CP_COMMIT();
    stage_load(sAb[1], sBb[1], rtRow, ctRow, 1, tid); CP_COMMIT();

    #pragma unroll
    for (int kc = 0; kc < 4; kc++) {
        if (kc == 3) CP_WAIT(0); else CP_WAIT(1);
        __syncthreads();
        int buf = kc & 1;
        #pragma unroll
        for (int ks = 0; ks < 4; ks++) {
            int k0 = ks * 16;
            uint32_t a[4][4], b[4][2];
            #pragma unroll
            for (int mt = 0; mt < 4; mt++)
                ldmA_sw(a[mt], sAb[buf], wr * 64 + mt * 16, k0, lane);
            #pragma unroll
            for (int nt = 0; nt < 4; nt++)
                ldmB_sw(b[nt], sBb[buf], wc * 32 + nt * 8, k0, lane);
            #pragma unroll
            for (int mt = 0; mt < 4; mt++)
                #pragma unroll
                for (int nt = 0; nt < 4; nt++)
                    mma_f16acc(acc[mt][nt], a[mt], b[nt]);
        }
        if (kc < 2) {
            __syncthreads();
            stage_load(sAb[buf], sBb[buf], rtRow, ctRow, kc + 2, tid);
            CP_COMMIT();
        }
    }

    float rAcc[4][2] = {};
    float cAcc[4][2] = {};
    #pragma unroll
    for (int mt = 0; mt < 4; mt++)
        #pragma unroll
        for (int nt = 0; nt < 4; nt++)
            #pragma unroll
            for (int h = 0; h < 2; h++) {
                __half2 pk = *(__half2*)&acc[mt][nt][h];
                float a0 = __low2float(pk), a1 = __high2float(pk);
                float v0 = fexp2(fmaf(a0, LOG2E_X2, -LOG2E_X2));
                float v1 = fexp2(fmaf(a1, LOG2E_X2, -LOG2E_X2));
                rAcc[mt][h] += v0 + v1;
                cAcc[nt][0] += v0;
                cAcc[nt][1] += v1;
            }

    #pragma unroll
    for (int mt = 0; mt < 4; mt++)
        #pragma unroll
        for (int h = 0; h < 2; h++) {
            float v = rAcc[mt][h];
            v += __shfl_xor_sync(0xFFFFFFFFu, v, 1);
            v += __shfl_xor_sync(0xFFFFFFFFu, v, 2);
            if ((lane & 3) == 0) {
                int row = rtRow + wr * 64 + mt * 16 + (lane >> 2) + h * 8;
                atomicAdd(&g_neg_sum[row], v);
            }
        }
    #pragma unroll
    for (int nt = 0; nt < 4; nt++)
        #pragma unroll
        for (int cc = 0; cc < 2; cc++) {
            float v = cAcc[nt][cc];
            v += __shfl_xor_sync(0xFFFFFFFFu, v, 4);
            v += __shfl_xor_sync(0xFFFFFFFFu, v, 8);
            v += __shfl_xor_sync(0xFFFFFFFFu, v, 16);
            if (lane < 4) {
                int col = ctRow + wc * 32 + nt * 8 + 2 * lane + cc;
                atomicAdd(&g_neg_sum[col], v);
            }
        }
}

// ---------------------------------------------------------------------------
// K3 (k_pos): ONE pair per block (early exit), same fully-unrolled 4-chunk
// 2-stage cp.async ring, f32 accumulators, launch_bounds(256,2) for 2 CTA/SM.
// Symmetric scatter; logS / invS inline.
// ---------------------------------------------------------------------------
extern "C" __global__ void __launch_bounds__(256, 2)
k_pos() {
    int bx = blockIdx.x;
    if (bx >= g_poscnt) return;
    unsigned p = g_pospairs[bx];
    int rt = (int)(p >> 8), ct = (int)(p & 255);
    bool diag = (rt == ct);
    int rtRow = rt * TILE, ctRow = ct * TILE;

    extern __shared__ __align__(16) char dynsm[];
    uint32_t smb = (uint32_t)__cvta_generic_to_shared(dynsm);
    uint32_t sAb[2] = { smb, smb + 2 * CHUNK_BYTES };
    uint32_t sBb[2] = { smb + CHUNK_BYTES, smb + 3 * CHUNK_BYTES };

    int tid  = threadIdx.x;
    int lane = tid & 31;
    int wid  = tid >> 5;
    int wr   = wid >> 2;
    int wc   = wid & 3;

    float acc[4][4][4];
    #pragma unroll
    for (int mt = 0; mt < 4; mt++)
        #pragma unroll
        for (int nt = 0; nt < 4; nt++)
            #pragma unroll
            for (int q = 0; q < 4; q++) acc[mt][nt][q] = 0.0f;

    stage_load(sAb[0], sBb[0], rtRow, ctRow, 0, tid); CP_COMMIT();
    stage_load(sAb[1], sBb[1], rtRow, ctRow, 1, tid); CP_COMMIT();

    #pragma unroll
    for (int kc = 0; kc < 4; kc++) {
        if (kc == 3) CP_WAIT(0); else CP_WAIT(1);
        __syncthreads();
        int buf = kc & 1;
        #pragma unroll
        for (int ks = 0; ks < 4; ks++) {
            int k0 = ks * 16;
            uint32_t a[4][4], b[4][2];
            #pragma unroll
            for (int mt = 0; mt < 4; mt++)
                ldmA_sw(a[mt], sAb[buf], wr * 64 + mt * 16, k0, lane);
            #pragma unroll
            for (int nt = 0; nt < 4; nt++)
                ldmB_sw(b[nt], sBb[buf], wc * 32 + nt * 8, k0, lane);
            #pragma unroll
            for (int mt = 0; mt < 4; mt++)
                #pragma unroll
                for (int nt = 0; nt < 4; nt++)
                    mma_f32acc(acc[mt][nt], a[mt], b[nt]);
        }
        if (kc < 2) {
            __syncthreads();
            stage_load(sAb[buf], sBb[buf], rtRow, ctRow, kc + 2, tid);
            CP_COMMIT();
        }
    }

    float cLog[4][2], cInv[4][2];
    float cSum[4][2] = {};
    #pragma unroll
    for (int nt = 0; nt < 4; nt++)
        #pragma unroll
        for (int cc = 0; cc < 2; cc++) {
            int col = ctRow + wc * 32 + nt * 8 + ((lane & 3) << 1) + cc;
            float S = g_neg_sum[col];
            cLog[nt][cc] = __logf(S);
            cInv[nt][cc] = 1.0f / S;
        }

    #pragma unroll
    for (int mt = 0; mt < 4; mt++) {
        #pragma unroll
        for (int h = 0; h < 2; h++) {
            int row  = rtRow + wr * 64 + mt * 16 + (lane >> 2) + h * 8;
            float Sr = g_neg_sum[row];
            float ls = __logf(Sr);
            float is = 1.0f / Sr;
            float rSum = 0.0f;
            #pragma unroll
            for (int nt = 0; nt < 4; nt++) {
                #pragma unroll
                for (int cc = 0; cc < 2; cc++) {
                    int col = ctRow + wc * 32 + nt * 8 + ((lane & 3) << 1) + cc;
                    if (diag && col == row) continue;
                    float a = acc[mt][nt][h * 2 + cc];
                    float l = fmaf(2.0f, a, -2.0f);
                    float e = fexp2(l * LOG2E);
                    float xr = e * is;
                    rSum += l - ls - xr + 0.5f * xr * xr;
                    if (!diag) {
                        float xc = e * cInv[nt][cc];
                        cSum[nt][cc] += l - cLog[nt][cc] - xc + 0.5f * xc * xc;
                    }
                }
            }
            float v = rSum;
            v += __shfl_xor_sync(0xFFFFFFFFu, v, 1);
            v += __shfl_xor_sync(0xFFFFFFFFu, v, 2);
            if ((lane & 3) == 0) atomicAdd(&g_row_loss[row], v);
        }
    }
    if (!diag) {
        #pragma unroll
        for (int nt = 0; nt < 4; nt++)
            #pragma unroll
            for (int cc = 0; cc < 2; cc++) {
                float v = cSum[nt][cc];
                v += __shfl_xor_sync(0xFFFFFFFFu, v, 4);
                v += __shfl_xor_sync(0xFFFFFFFFu, v, 8);
                v += __shfl_xor_sync(0xFFFFFFFFu, v, 16);
                if (lane < 4) {
                    int col = ctRow + wc * 32 + nt * 8 + 2 * lane + cc;
                    atomicAdd(&g_row_loss[col], v);
                }
            }
    }
}

// ---------------------------------------------------------------------------
// K4: final reduction
// ---------------------------------------------------------------------------
__global__ void k_final(const int* __restrict__ labels, float* __restrict__ out) {
    __shared__ int   lab[TT];
    __shared__ float invpc[TT];
    __shared__ float ws[8];
    int tid = threadIdx.x;
    if (tid < TT) lab[tid] = labels[tid];
    __syncthreads();
    if (tid < TT) {
        int ns = 0;
        #pragma unroll
        for (int j = 0; j < TT; j++) ns += (lab[j] == lab[tid]);
        invpc[tid] = 1.0f / (float)(ns * VV - 1);
    }
    __syncthreads();

    float s = 0.0f;
    for (int i = tid; i < TV; i += 256) s += g_row_loss[i] * invpc[i >> 8];
    #pragma unroll
    for (int o = 16; o; o >>= 1) s += __shfl_xor_sync(0xFFFFFFFFu, s, o);
    if ((tid & 31) == 0) ws[tid >> 5] = s;
    __syncthreads();
    if (tid == 0) {
        float t = 0.0f;
        #pragma unroll
        for (int w = 0; w < 8; w++) t += ws[w];
        out[0] = -(t / (float)TV);
    }
}

// ---------------------------------------------------------------------------
extern "C" void kernel_launch(void* const* d_in, const int* in_sizes, int n_in,
                              void* d_out, int out_size) {
    const float* features    = (const float*)d_in[0];
    const int*   batch_inds  = (const int*)d_in[1];
    const void*  sample_inds = (const void*)d_in[2];
    const int*   labels      = (const int*)d_in[3];
    float*       out         = (float*)d_out;

    static bool attr_set = false;
    if (!attr_set) {
        cudaFuncSetAttribute(k_negpair, cudaFuncAttributeMaxDynamicSharedMemorySize, SMEM_BYTES_RING);
        cudaFuncSetAttribute(k_pos,     cudaFuncAttributeMaxDynamicSharedMemorySize, SMEM_BYTES_RING);
        attr_set = true;
    }

    k_prep<<<1, 256>>>((const unsigned int*)sample_inds, labels);
    k_gather<<<TV / 8, 256>>>(features, batch_inds, sample_inds);
    k_negpair<<<MAXNEG, 256, SMEM_BYTES_RING>>>();
    k_pos<<<MAXPOS, 256, SMEM_BYTES_RING>>>();
    k_final<<<1, 256>>>(labels, out);
}

// round 15
// speedup vs baseline: 1.6711x; 1.0206x over previous
#include <cuda_runtime.h>
#include <cuda_fp16.h>
#include <cstdint>

// Problem constants
#define NIMG   8
#define CDIM   256
#define HWDIM  9216
#define TT     32
#define VV     256
#define TV     8192
#define TILE   128
#define NTILES 64

// chunked smem: XOR-swizzled 128x64 chunks (16 KB each)
#define CHUNK_BYTES 16384
// k_negpair: 2 stages x (A, B1, B2) = 6 chunks = 96 KB
#define SMEM_BYTES_NEG (6 * CHUNK_BYTES)
// k_pos: 2 stages x (A, B) = 4 chunks = 64 KB
#define SMEM_BYTES_POS (4 * CHUNK_BYTES)

#define MAXNEGI 1056      // grouped (rt, ct1, ct2) items
#define MAXPOS  2080

#define LOG2E    1.4426950408889634f
#define LOG2E_X2 2.8853900817779268f           // exp(2a-2) = 2^(a*L2 - L2)

// Persistent device scratch
__device__ __half g_feats[(size_t)TV * CDIM];
__device__ float g_neg_sum[TV];
__device__ float g_row_loss[TV];
__device__ int   g_is64;
__device__ int   g_negcnt;                     // item count (grouped)
__device__ int   g_poscnt;
__device__ unsigned int   g_negitems[MAXNEGI]; // rt | ct1<<8 | ct2<<16 (0xFF = none)
__device__ unsigned short g_pospairs[MAXPOS];

__device__ __forceinline__ float fexp2(float x) {
    float r;
    asm("ex2.approx.f32 %0, %1;" : "=f"(r) : "f"(x));
    return r;
}

#define CP_ASYNC16(dst, src) \
    asm volatile("cp.async.cg.shared.global [%0], [%1], 16;" :: "r"(dst), "l"(src))
#define CP_COMMIT()  asm volatile("cp.async.commit_group;" ::: "memory")
#define CP_WAIT(n)   asm volatile("cp.async.wait_group %0;" :: "n"(n) : "memory")

// ---------------------------------------------------------------------------
// K_prep: 1 block. dtype detect + zero accumulators + worklist build.
// Neg worklist grouped by row tile: thread per rt pairs up its negative cts.
// ---------------------------------------------------------------------------
__global__ void k_prep(const unsigned int* __restrict__ w,
                       const int* __restrict__ labels) {
    int tid = threadIdx.x;
    unsigned acc = 0;
    for (int i = tid; i < 4096; i += 256) acc |= w[2 * i + 1];
    #pragma unroll
    for (int o = 16; o; o >>= 1) acc |= __shfl_xor_sync(0xFFFFFFFFu, acc, o);
    __shared__ unsigned sh[8];
    if ((tid & 31) == 0) sh[tid >> 5] = acc;
    for (int i = tid; i < TV; i += 256) { g_neg_sum[i] = 0.0f; g_row_loss[i] = 0.0f; }
    if (tid == 0) { g_negcnt = 0; g_poscnt = 0; }
    __syncthreads();
    if (tid == 0) {
        unsigned t = 0;
        #pragma unroll
        for (int i = 0; i < 8; i++) t |= sh[i];
        g_is64 = (t == 0) ? 1 : 0;
    }
    __shared__ int slab[TT];
    if (tid < TT) slab[tid] = labels[tid];
    __syncthreads();

    // grouped negative items: one thread per rt
    if (tid < NTILES) {
        int rt = tid;
        int Lr = slab[rt >> 1];
        int cts[NTILES];
        int n = 0;
        for (int ct = rt + 1; ct < NTILES; ct++)
            if (slab[ct >> 1] != Lr) cts[n++] = ct;
        int items = (n + 1) >> 1;
        if (items > 0) {
            int base = atomicAdd(&g_negcnt, items);
            for (int i = 0; i < items; i++) {
                int c1 = cts[2 * i];
                int c2 = (2 * i + 1 < n) ? cts[2 * i + 1] : 0xFF;
                g_negitems[base + i] =
                    (unsigned)rt | ((unsigned)c1 << 8) | ((unsigned)c2 << 16);
            }
        }
    }
    // positive pairs (unordered, incl. diagonal)
    for (int idx = tid; idx < NTILES * NTILES; idx += 256) {
        int rt = idx >> 6, ct = idx & 63;
        if (ct < rt) continue;
        if (slab[rt >> 1] == slab[ct >> 1])
            g_pospairs[atomicAdd(&g_poscnt, 1)] = (unsigned short)((rt << 8) | ct);
    }
}

// ---------------------------------------------------------------------------
// K1: gather + L2-normalize -> fp16. Warp per sample; 8 strided loads.
// ---------------------------------------------------------------------------
__global__ void __launch_bounds__(256)
k_gather(const float* __restrict__ features,
         const int* __restrict__ batch_inds,
         const void* __restrict__ sample_inds) {
    __shared__ __half stage[8 * 264];
    int tid  = threadIdx.x;
    int lane = tid & 31;
    int wrp  = tid >> 5;
    int i = blockIdx.x * 8 + wrp;
    int t = i >> 8;
    int v = i & 255;
    int b = batch_inds[t] & (NIMG - 1);

    long long s;
    if (g_is64) s = ((const long long*)sample_inds)[t * VV + v];
    else        s = (long long)((const int*)sample_inds)[t * VV + v];
    if (s < 0) s = 0;
    if (s >= HWDIM) s = HWDIM - 1;

    const float* base = features + (size_t)b * CDIM * HWDIM + (size_t)s;
    float f[8];
    #pragma unroll
    for (int k = 0; k < 8; k++)
        f[k] = base[(size_t)(lane + 32 * k) * HWDIM];

    float ss = 0.0f;
    #pragma unroll
    for (int k = 0; k < 8; k++) ss += f[k] * f[k];
    #pragma unroll
    for (int o = 16; o; o >>= 1) ss += __shfl_xor_sync(0xFFFFFFFFu, ss, o);

    float inv = 1.0f / fmaxf(sqrtf(ss), 1e-12f);
    #pragma unroll
    for (int k = 0; k < 8; k++)
        stage[wrp * 264 + lane + 32 * k] = __float2half(f[k] * inv);
    __syncwarp();
    uint4 val = *(uint4*)&stage[wrp * 264 + lane * 8];
    *(uint4*)(g_feats + (size_t)i * CDIM + lane * 8) = val;
}

// ---------------------------------------------------------------------------
// swizzled ldmatrix / mma helpers
// ---------------------------------------------------------------------------
__device__ __forceinline__ void ldmA_sw(uint32_t a[4], uint32_t base,
                                        int rowBase, int k0, int lane) {
    int row = rowBase + (lane & 15);
    int u   = (k0 >> 3) + (lane >> 4);
    uint32_t addr = base + (uint32_t)((row * 8 + (u ^ (row & 7))) * 16);
    asm volatile("ldmatrix.sync.aligned.m8n8.x4.shared.b16 {%0,%1,%2,%3}, [%4];"
                 : "=r"(a[0]), "=r"(a[1]), "=r"(a[2]), "=r"(a[3]) : "r"(addr));
}
__device__ __forceinline__ void ldmB_sw(uint32_t b[2], uint32_t base,
                                        int nBase, int k0, int lane) {
    int l   = lane & 15;
    int row = nBase + (l & 7);
    int u   = (k0 >> 3) + (l >> 3);
    uint32_t addr = base + (uint32_t)((row * 8 + (u ^ (row & 7))) * 16);
    asm volatile("ldmatrix.sync.aligned.m8n8.x2.shared.b16 {%0,%1}, [%2];"
                 : "=r"(b[0]), "=r"(b[1]) : "r"(addr));
}
__device__ __forceinline__ void mma_f16acc(uint32_t c[2], const uint32_t a[4],
                                           const uint32_t b[2]) {
    asm volatile("mma.sync.aligned.m16n8k16.row.col.f16.f16.f16.f16 "
                 "{%0,%1},{%2,%3,%4,%5},{%6,%7},{%0,%1};"
                 : "+r"(c[0]), "+r"(c[1])
                 : "r"(a[0]), "r"(a[1]), "r"(a[2]), "r"(a[3]), "r"(b[0]), "r"(b[1]));
}
__device__ __forceinline__ void mma_f32acc(float c[4], const uint32_t a[4],
                                           const uint32_t b[2]) {
    asm volatile("mma.sync.aligned.m16n8k16.row.col.f32.f16.f16.f32 "
                 "{%0,%1,%2,%3},{%4,%5,%6,%7},{%8,%9},{%0,%1,%2,%3};"
                 : "+f"(c[0]), "+f"(c[1]), "+f"(c[2]), "+f"(c[3])
                 : "r"(a[0]), "r"(a[1]), "r"(a[2]), "r"(a[3]), "r"(b[0]), "r"(b[1]));
}

// cp.async one K-chunk stage: 2 tiles (A, B)
__device__ __forceinline__ void stage_load(uint32_t sA, uint32_t sB,
                                           int rtRow, int ctRow, int kc, int tid) {
    #pragma unroll
    for (int x = 0; x < 4; x++) {
        int idx = tid + x * 256;
        int row = idx >> 3;
        int u   = idx & 7;
        uint32_t doff = (uint32_t)((row * 8 + (u ^ (row & 7))) * 16);
        const char* srcA = (const char*)(g_feats
                          + ((size_t)(rtRow + row) << 8) + kc * 64 + u * 8);
        const char* srcB = (const char*)(g_feats
                          + ((size_t)(ctRow + row) << 8) + kc * 64 + u * 8);
        CP_ASYNC16(sA + doff, srcA);
        CP_ASYNC16(sB + doff, srcB);
    }
}
// cp.async one K-chunk stage: 3 tiles (A, B1, B2)
__device__ __forceinline__ void stage_load3(uint32_t sA, uint32_t sB1, uint32_t sB2,
                                            int rtRow, int c1Row, int c2Row,
                                            int kc, int tid) {
    #pragma unroll
    for (int x = 0; x < 4; x++) {
        int idx = tid + x * 256;
        int row = idx >> 3;
        int u   = idx & 7;
        uint32_t doff = (uint32_t)((row * 8 + (u ^ (row & 7))) * 16);
        const char* srcA = (const char*)(g_feats
                          + ((size_t)(rtRow + row) << 8) + kc * 64 + u * 8);
        const char* src1 = (const char*)(g_feats
                          + ((size_t)(c1Row + row) << 8) + kc * 64 + u * 8);
        const char* src2 = (const char*)(g_feats
                          + ((size_t)(c2Row + row) << 8) + kc * 64 + u * 8);
        CP_ASYNC16(sA  + doff, srcA);
        CP_ASYNC16(sB1 + doff, src1);
        CP_ASYNC16(sB2 + doff, src2);
    }
}

// ---------------------------------------------------------------------------
// K2 (k_negpair): grouped item (rt, ct1, ct2) per block. A fragments loaded
// once per K-step, reused for both B tiles. f16 acc; 2-stage cp.async ring.
// ---------------------------------------------------------------------------
extern "C" __global__ void __launch_bounds__(256, 2)
k_negpair() {
    int bx = blockIdx.x;
    if (bx >= g_negcnt) return;
    unsigned it = g_negitems[bx];
    int rt = (int)(it & 255);
    int c1 = (int)((it >> 8) & 255);
    int c2 = (int)((it >> 16) & 255);
    bool has2 = (c2 != 255);
    int c2e = has2 ? c2 : c1;
    int rtRow = rt * TILE, c1Row = c1 * TILE, c2Row = c2e * TILE;

    extern __shared__ __align__(16) char dynsm[];
    uint32_t smb = (uint32_t)__cvta_generic_to_shared(dynsm);
    uint32_t sAb[2]  = { smb,                   smb + 3 * CHUNK_BYTES };
    uint32_t sB1b[2] = { smb + CHUNK_BYTES,     smb + 4 * CHUNK_BYTES };
    uint32_t sB2b[2] = { smb + 2 * CHUNK_BYTES, smb + 5 * CHUNK_BYTES };

    int tid  = threadIdx.x;
    int lane = tid & 31;
    int wid  = tid >> 5;
    int wr   = wid >> 2;
    int wc   = wid & 3;

    uint32_t acc1[4][4][2], acc2[4][4][2];
    #pragma unroll
    for (int mt = 0; mt < 4; mt++)
        #pragma unroll
        for (int nt = 0; nt < 4; nt++) {
            acc1[mt][nt][0] = 0u; acc1[mt][nt][1] = 0u;
            acc2[mt][nt][0] = 0u; acc2[mt][nt][1] = 0u;
        }

    stage_load3(sAb[0], sB1b[0], sB2b[0], rtRow, c1Row, c2Row, 0, tid); CP_COMMIT();
    stage_load3(sAb[1], sB1b[1], sB2b[1], rtRow, c1Row, c2Row, 1, tid); CP_COMMIT();

    #pragma unroll
    for (int kc = 0; kc < 4; kc++) {
        if (kc == 3) CP_WAIT(0); else CP_WAIT(1);
        __syncthreads();
        int buf = kc & 1;
        #pragma unroll
        for (int ks = 0; ks < 4; ks++) {
            int k0 = ks * 16;
            uint32_t a[4][4], b[4][2];
            #pragma unroll
            for (int mt = 0; mt < 4; mt++)
                ldmA_sw(a[mt], sAb[buf], wr * 64 + mt * 16, k0, lane);
            // tile 1
            #pragma unroll
            for (int nt = 0; nt < 4; nt++)
                ldmB_sw(b[nt], sB1b[buf], wc * 32 + nt * 8, k0, lane);
            #pragma unroll
            for (int mt = 0; mt < 4; mt++)
                #pragma unroll
                for (int nt = 0; nt < 4; nt++)
                    mma_f16acc(acc1[mt][nt], a[mt], b[nt]);
            // tile 2 (reuse b regs)
            #pragma unroll
            for (int nt = 0; nt < 4; nt++)
                ldmB_sw(b[nt], sB2b[buf], wc * 32 + nt * 8, k0, lane);
            #pragma unroll
            for (int mt = 0; mt < 4; mt++)
                #pragma unroll
                for (int nt = 0; nt < 4; nt++)
                    mma_f16acc(acc2[mt][nt], a[mt], b[nt]);
        }
        if (kc < 2) {
            __syncthreads();
            stage_load3(sAb[buf], sB1b[buf], sB2b[buf],
                        rtRow, c1Row, c2Row, kc + 2, tid);
            CP_COMMIT();
        }
    }

    // epilogue: tile 1 always; tile 2 only if valid. Rows accumulate both.
    float rAcc[4][2] = {};
    float c1Acc[4][2] = {};
    float c2Acc[4][2] = {};
    #pragma unroll
    for (int mt = 0; mt < 4; mt++)
        #pragma unroll
        for (int nt = 0; nt < 4; nt++)
            #pragma unroll
            for (int h = 0; h < 2; h++) {
                __half2 pk = *(__half2*)&acc1[mt][nt][h];
                float a0 = __low2float(pk), a1 = __high2float(pk);
                float v0 = fexp2(fmaf(a0, LOG2E_X2, -LOG2E_X2));
                float v1 = fexp2(fmaf(a1, LOG2E_X2, -LOG2E_X2));
                rAcc[mt][h] += v0 + v1;
                c1Acc[nt][0] += v0;
                c1Acc[nt][1] += v1;
            }
    if (has2) {
        #pragma unroll
        for (int mt = 0; mt < 4; mt++)
            #pragma unroll
            for (int nt = 0; nt < 4; nt++)
                #pragma unroll
                for (int h = 0; h < 2; h++) {
                    __half2 pk = *(__half2*)&acc2[mt][nt][h];
                    float a0 = __low2float(pk), a1 = __high2float(pk);
                    float v0 = fexp2(fmaf(a0, LOG2E_X2, -LOG2E_X2));
                    float v1 = fexp2(fmaf(a1, LOG2E_X2, -LOG2E_X2));
                    rAcc[mt][h] += v0 + v1;
                    c2Acc[nt][0] += v0;
                    c2Acc[nt][1] += v1;
                }
    }

    #pragma unroll
    for (int mt = 0; mt < 4; mt++)
        #pragma unroll
        for (int h = 0; h < 2; h++) {
            float v = rAcc[mt][h];
            v += __shfl_xor_sync(0xFFFFFFFFu, v, 1);
            v += __shfl_xor_sync(0xFFFFFFFFu, v, 2);
            if ((lane & 3) == 0) {
                int row = rtRow + wr * 64 + mt * 16 + (lane >> 2) + h * 8;
                atomicAdd(&g_neg_sum[row], v);
            }
        }
    #pragma unroll
    for (int nt = 0; nt < 4; nt++)
        #pragma unroll
        for (int cc = 0; cc < 2; cc++) {
            float v = c1Acc[nt][cc];
            v += __shfl_xor_sync(0xFFFFFFFFu, v, 4);
            v += __shfl_xor_sync(0xFFFFFFFFu, v, 8);
            v += __shfl_xor_sync(0xFFFFFFFFu, v, 16);
            if (lane < 4) {
                int col = c1Row + wc * 32 + nt * 8 + 2 * lane + cc;
                atomicAdd(&g_neg_sum[col], v);
            }
        }
    if (has2) {
        #pragma unroll
        for (int nt = 0; nt < 4; nt++)
            #pragma unroll
            for (int cc = 0; cc < 2; cc++) {
                float v = c2Acc[nt][cc];
                v += __shfl_xor_sync(0xFFFFFFFFu, v, 4);
                v += __shfl_xor_sync(0xFFFFFFFFu, v, 8);
                v += __shfl_xor_sync(0xFFFFFFFFu, v, 16);
                if (lane < 4) {
                    int col = c2Row + wc * 32 + nt * 8 + 2 * lane + cc;
                    atomicAdd(&g_neg_sum[col], v);
                }
            }
    }
}

// ---------------------------------------------------------------------------
// K3 (k_pos): R13 version (validated 16.9us). One pair per block; 4-chunk
// 2-stage cp.async ring; f32 acc; symmetric scatter; logS/invS inline.
// ---------------------------------------------------------------------------
extern "C" __global__ void __launch_bounds__(256, 2)
k_pos() {
    int bx = blockIdx.x;
    if (bx >= g_poscnt) return;
    unsigned p = g_pospairs[bx];
    int rt = (int)(p >> 8), ct = (int)(p & 255);
    bool diag = (rt == ct);
    int rtRow = rt * TILE, ctRow = ct * TILE;

    extern __shared__ __align__(16) char dynsm[];
    uint32_t smb = (uint32_t)__cvta_generic_to_shared(dynsm);
    uint32_t sAb[2] = { smb, smb + 2 * CHUNK_BYTES };
    uint32_t sBb[2] = { smb + CHUNK_BYTES, smb + 3 * CHUNK_BYTES };

    int tid  = threadIdx.x;
    int lane = tid & 31;
    int wid  = tid >> 5;
    int wr   = wid >> 2;
    int wc   = wid & 3;

    float acc[4][4][4];
    #pragma unroll
    for (int mt = 0; mt < 4; mt++)
        #pragma unroll
        for (int nt = 0; nt < 4; nt++)
            #pragma unroll
            for (int q = 0; q < 4; q++) acc[mt][nt][q] = 0.0f;

    stage_load(sAb[0], sBb[0], rtRow, ctRow, 0, tid); CP_COMMIT();
    stage_load(sAb[1], sBb[1], rtRow, ctRow, 1, tid); CP_COMMIT();

    #pragma unroll
    for (int kc = 0; kc < 4; kc++) {
        if (kc == 3) CP_WAIT(0); else CP_WAIT(1);
        __syncthreads();
        int buf = kc & 1;
        #pragma unroll
        for (int ks = 0; ks < 4; ks++) {
            int k0 = ks * 16;
            uint32_t a[4][4], b[4][2];
            #pragma unroll
            for (int mt = 0; mt < 4; mt++)
                ldmA_sw(a[mt], sAb[buf], wr * 64 + mt * 16, k0, lane);
            #pragma unroll
            for (int nt = 0; nt < 4; nt++)
                ldmB_sw(b[nt], sBb[buf], wc * 32 + nt * 8, k0, lane);
            #pragma unroll
            for (int mt = 0; mt < 4; mt++)
                #pragma unroll
                for (int nt = 0; nt < 4; nt++)
                    mma_f32acc(acc[mt][nt], a[mt], b[nt]);
        }
        if (kc < 2) {
            __syncthreads();
            stage_load(sAb[buf], sBb[buf], rtRow, ctRow, kc + 2, tid);
            CP_COMMIT();
        }
    }

    float cLog[4][2], cInv[4][2];
    float cSum[4][2] = {};
    #pragma unroll
    for (int nt = 0; nt < 4; nt++)
        #pragma unroll
        for (int cc = 0; cc < 2; cc++) {
            int col = ctRow + wc * 32 + nt * 8 + ((lane & 3) << 1) + cc;
            float S = g_neg_sum[col];
            cLog[nt][cc] = __logf(S);
            cInv[nt][cc] = 1.0f / S;
        }

    #pragma unroll
    for (int mt = 0; mt < 4; mt++) {
        #pragma unroll
        for (int h = 0; h < 2; h++) {
            int row  = rtRow + wr * 64 + mt * 16 + (lane >> 2) + h * 8;
            float Sr = g_neg_sum[row];
            float ls = __logf(Sr);
            float is = 1.0f / Sr;
            float rSum = 0.0f;
            #pragma unroll
            for (int nt = 0; nt < 4; nt++) {
                #pragma unroll
                for (int cc = 0; cc < 2; cc++) {
                    int col = ctRow + wc * 32 + nt * 8 + ((lane & 3) << 1) + cc;
                    if (diag && col == row) continue;
                    float a = acc[mt][nt][h * 2 + cc];
                    float l = fmaf(2.0f, a, -2.0f);
                    float e = fexp2(l * LOG2E);
                    float xr = e * is;
                    rSum += l - ls - xr + 0.5f * xr * xr;
                    if (!diag) {
                        float xc = e * cInv[nt][cc];
                        cSum[nt][cc] += l - cLog[nt][cc] - xc + 0.5f * xc * xc;
                    }
                }
            }
            float v = rSum;
            v += __shfl_xor_sync(0xFFFFFFFFu, v, 1);
            v += __shfl_xor_sync(0xFFFFFFFFu, v, 2);
            if ((lane & 3) == 0) atomicAdd(&g_row_loss[row], v);
        }
    }
    if (!diag) {
        #pragma unroll
        for (int nt = 0; nt < 4; nt++)
            #pragma unroll
            for (int cc = 0; cc < 2; cc++) {
                float v = cSum[nt][cc];
                v += __shfl_xor_sync(0xFFFFFFFFu, v, 4);
                v += __shfl_xor_sync(0xFFFFFFFFu, v, 8);
                v += __shfl_xor_sync(0xFFFFFFFFu, v, 16);
                if (lane < 4) {
                    int col = ctRow + wc * 32 + nt * 8 + 2 * lane + cc;
                    atomicAdd(&g_row_loss[col], v);
                }
            }
    }
}

// ---------------------------------------------------------------------------
// K4: final reduction
// ---------------------------------------------------------------------------
__global__ void k_final(const int* __restrict__ labels, float* __restrict__ out) {
    __shared__ int   lab[TT];
    __shared__ float invpc[TT];
    __shared__ float ws[8];
    int tid = threadIdx.x;
    if (tid < TT) lab[tid] = labels[tid];
    __syncthreads();
    if (tid < TT) {
        int ns = 0;
        #pragma unroll
        for (int j = 0; j < TT; j++) ns += (lab[j] == lab[tid]);
        invpc[tid] = 1.0f / (float)(ns * VV - 1);
    }
    __syncthreads();

    float s = 0.0f;
    for (int i = tid; i < TV; i += 256) s += g_row_loss[i] * invpc[i >> 8];
    #pragma unroll
    for (int o = 16; o; o >>= 1) s += __shfl_xor_sync(0xFFFFFFFFu, s, o);
    if ((tid & 31) == 0) ws[tid >> 5] = s;
    __syncthreads();
    if (tid == 0) {
        float t = 0.0f;
        #pragma unroll
        for (int w = 0; w < 8; w++) t += ws[w];
        out[0] = -(t / (float)TV);
    }
}

// ---------------------------------------------------------------------------
extern "C" void kernel_launch(void* const* d_in, const int* in_sizes, int n_in,
                              void* d_out, int out_size) {
    const float* features    = (const float*)d_in[0];
    const int*   batch_inds  = (const int*)d_in[1];
    const void*  sample_inds = (const void*)d_in[2];
    const int*   labels      = (const int*)d_in[3];
    float*       out         = (float*)d_out;

    static bool attr_set = false;
    if (!attr_set) {
        cudaFuncSetAttribute(k_negpair, cudaFuncAttributeMaxDynamicSharedMemorySize, SMEM_BYTES_NEG);
        cudaFuncSetAttribute(k_pos,     cudaFuncAttributeMaxDynamicSharedMemorySize, SMEM_BYTES_POS);
        attr_set = true;
    }

    k_prep<<<1, 256>>>((const unsigned int*)sample_inds, labels);
    k_gather<<<TV / 8, 256>>>(features, batch_inds, sample_inds);
    k_negpair<<<MAXNEGI, 256, SMEM_BYTES_NEG>>>();
    k_pos<<<MAXPOS, 256, SMEM_BYTES_POS>>>();
    k_final<<<1, 256>>>(labels, out);
}